// round 13
// baseline (speedup 1.0000x reference)
#include <cuda_runtime.h>

#define NCLS 32
#define SOSC 30
#define EOSC 31
#define LOG2E 1.4426950408889634f
#define LN2F  0.6931471805599453f
#define MAXB  8192

typedef unsigned long long u64;

__device__ float g_vec[2][MAXB][NCLS];   // [dir][batch][class] scan results
__device__ int   g_eC[2][MAXB];          // [dir][batch] exact log2 offsets

__device__ __forceinline__ float ex2f(float x){ float r; asm("ex2.approx.f32 %0, %1;" : "=f"(r) : "f"(x)); return r; }
__device__ __forceinline__ float lg2f_(float x){ float r; asm("lg2.approx.f32 %0, %1;" : "=f"(r) : "f"(x)); return r; }
__device__ __forceinline__ u64 pk2(float lo, float hi){ u64 r; asm("mov.b64 %0, {%1,%2};" : "=l"(r) : "f"(lo), "f"(hi)); return r; }
__device__ __forceinline__ void up2(u64 v, float& lo, float& hi){ asm("mov.b64 {%0,%1}, %2;" : "=f"(lo), "=f"(hi) : "l"(v)); }
__device__ __forceinline__ u64 ffma2(u64 a, u64 b, u64 c){ u64 d; asm("fma.rn.f32x2 %0, %1, %2, %3;" : "=l"(d) : "l"(a), "l"(b), "l"(c)); return d; }
__device__ __forceinline__ u64 fadd2(u64 a, u64 b){ u64 d; asm("add.rn.f32x2 %0, %1, %2;" : "=l"(d) : "l"(a), "l"(b)); return d; }
__device__ __forceinline__ u64 fmul2(u64 a, u64 b){ u64 d; asm("mul.rn.f32x2 %0, %1, %2;" : "=l"(d) : "l"(a), "l"(b)); return d; }
__device__ __forceinline__ u64 fsub2(u64 a, u64 b){ u64 d; asm("sub.rn.f32x2 %0, %1, %2;" : "=l"(d) : "l"(a), "l"(b)); return d; }

__device__ __forceinline__ u64 shfl64(u64 v, int src){
    float lo, hi; up2(v, lo, hi);
    lo = __shfl_sync(0xffffffffu, lo, src);
    hi = __shfl_sync(0xffffffffu, hi, src);
    return pk2(lo, hi);
}

// Exact power-of-2 rescale factor from a stale probe value d (pure ALU).
__device__ __forceinline__ float po2_rescale(float d, int& eacc){
    unsigned u = __float_as_uint(d);
    int e = (int)(u >> 23) & 0xff;
    if (e == 0 || e >= 254) return 1.0f;
    eacc += (e - 127);
    return __uint_as_float((unsigned)(254 - e) << 23);
}

// Bidirectional exp-domain CRF scan. The recurrence is linear:
//   P_{t+1} = M_t P_t,  M_t = m_t diag(fe_t) E + (1-m_t) I,
//   answer  = log(u^T M_{seq-1}...M_0 P_0),  u = exp(T[EOS]).
// CTA (1 warp, 2 batches) does either the forward half-scan (P_mid) or the
// backward row-vector half-scan (u_mid^T = u^T M_{seq-1}...M_mid, step:
// u <- m*E^T(u o fe) + (1-m)u). Same per-step cost both directions; warp
// layout/exchange/blend/rescale are exactly the proven round-9 pattern.
// Results land in g_vec/g_eC; crf_combine does out = ln2*(eCf+eCb+log2(P.u)).
__global__ __launch_bounds__(32, 14)
void crf_scan(const float* __restrict__ feats,
              const float* __restrict__ mask,
              const float* __restrict__ trans,
              int seq, int batch, int mid)
{
    const int lane = threadIdx.x & 31;
    const int b    = lane >> 4;       // batch slot (0..1)
    const int g    = lane & 15;
    const int gc   = g & 7;           // class group -> classes 4gc..4gc+3
    const int kh   = g >> 3;          // summation half: idx in [16*kh,16*kh+16)
    const int c0   = gc * 4;
    const int k0   = kh * 16;
    const int dirb = blockIdx.x & 1;  // 0 = forward, 1 = backward
    const int pair = blockIdx.x >> 1;
    int bb = pair * 2 + b;
    const bool real = (bb < batch);
    if (!real) bb = batch - 1;
    const int xbase = (lane & 16) | (kh << 2);

    // E2: forward = rows of exp(T); backward = rows of exp(T)^T (columns).
    u64 E2[4][8];
    if (dirb == 0){
#pragma unroll
        for (int ci = 0; ci < 4; ++ci){
            const float* tr = trans + (c0 + ci) * NCLS + k0;
#pragma unroll
            for (int kp = 0; kp < 8; ++kp)
                E2[ci][kp] = pk2(ex2f(tr[2*kp] * LOG2E), ex2f(tr[2*kp+1] * LOG2E));
        }
    } else {
#pragma unroll
        for (int ci = 0; ci < 4; ++ci){
#pragma unroll
            for (int kp = 0; kp < 8; ++kp)
                E2[ci][kp] = pk2(ex2f(trans[(k0 + 2*kp    ) * NCLS + c0 + ci] * LOG2E),
                                 ex2f(trans[(k0 + 2*kp + 1) * NCLS + c0 + ci] * LOG2E));
        }
    }

    // State init: fwd = SOS one-hot; bwd = exp(T[EOS, c]).
    u64 P2[2];
    if (dirb == 0){
        P2[0] = pk2((c0+0==SOSC)?1.f:0.f, (c0+1==SOSC)?1.f:0.f);
        P2[1] = pk2((c0+2==SOSC)?1.f:0.f, (c0+3==SOSC)?1.f:0.f);
    } else {
        const float* te = trans + EOSC * NCLS + c0;
        P2[0] = pk2(ex2f(te[0]*LOG2E), ex2f(te[1]*LOG2E));
        P2[1] = pk2(ex2f(te[2]*LOG2E), ex2f(te[3]*LOG2E));
    }
    int eC = 0;

    const float* fbase = feats + (size_t)bb * NCLS + c0;
    const float* mbase = mask + bb;
    const unsigned fstep = (unsigned)batch * NCLS;
    const unsigned mstep = (unsigned)batch;

    // Step schedule: fwd walks t = 0..mid-1; bwd walks t = seq-1..mid.
    const int n    = (dirb == 0) ? mid : (seq - mid);
    const int tbeg = (dirb == 0) ? 0 : (seq - 1);
    const int dt   = (dirb == 0) ? 1 : -1;
    const int tlast = tbeg + dt * (n - 1);

    // 4-deep prefetch of exp(feat) and packed mask.
    u64 fe[4][2], mm[4];
#pragma unroll
    for (int j = 0; j < 4; ++j){
        int tc = (j < n) ? (tbeg + dt * j) : tlast;
        if (n <= 0) tc = tbeg >= 0 ? (tbeg < seq ? tbeg : seq - 1) : 0;  // degenerate
        float4 f4 = *reinterpret_cast<const float4*>(fbase + (size_t)((unsigned)tc * fstep));
        fe[j][0] = pk2(ex2f(f4.x*LOG2E), ex2f(f4.y*LOG2E));
        fe[j][1] = pk2(ex2f(f4.z*LOG2E), ex2f(f4.w*LOG2E));
        float m = mbase[(unsigned)tc * mstep];
        mm[j] = pk2(m, m);
    }

    int done = 0;
    while (done + 4 <= n){
#pragma unroll
        for (int j = 0; j < 4; ++j){
            // stale rescale pivot from pre-step state (ALU+shfl, overlaps body)
            float r = 1.0f;
            if (j == 0){
                float plo, phi; up2(P2[0], plo, phi);
                float piv = __shfl_sync(0xffffffffu, plo, lane & 16);
                r = po2_rescale(piv, eC);
            }
            u64 Pn0, Pn1;
            if (dirb == 0){
                // q = exchange(P); s = E q; Pn = s o fe
                u64 q[8];
#pragma unroll
                for (int qi = 0; qi < 4; ++qi){
                    q[2*qi]   = shfl64(P2[0], xbase + qi);
                    q[2*qi+1] = shfl64(P2[1], xbase + qi);
                }
                float s[4];
#pragma unroll
                for (int ci = 0; ci < 4; ++ci){
                    u64 aA = 0ull, aB = 0ull;
                    aA = ffma2(E2[ci][0], q[0], aA);
                    aB = ffma2(E2[ci][1], q[1], aB);
                    aA = ffma2(E2[ci][2], q[2], aA);
                    aB = ffma2(E2[ci][3], q[3], aB);
                    aA = ffma2(E2[ci][4], q[4], aA);
                    aB = ffma2(E2[ci][5], q[5], aB);
                    aA = ffma2(E2[ci][6], q[6], aA);
                    aB = ffma2(E2[ci][7], q[7], aB);
                    u64 a = fadd2(aA, aB);
                    float lo, hi; up2(a, lo, hi);
                    s[ci] = lo + hi;
                }
#pragma unroll
                for (int ci = 0; ci < 4; ++ci)
                    s[ci] += __shfl_xor_sync(0xffffffffu, s[ci], 8);
                Pn0 = fmul2(pk2(s[0], s[1]), fe[j][0]);
                Pn1 = fmul2(pk2(s[2], s[3]), fe[j][1]);
            } else {
                // v = u o fe; q = exchange(v); Pn = E^T q
                u64 v0 = fmul2(P2[0], fe[j][0]);
                u64 v1 = fmul2(P2[1], fe[j][1]);
                u64 q[8];
#pragma unroll
                for (int qi = 0; qi < 4; ++qi){
                    q[2*qi]   = shfl64(v0, xbase + qi);
                    q[2*qi+1] = shfl64(v1, xbase + qi);
                }
                float s[4];
#pragma unroll
                for (int ci = 0; ci < 4; ++ci){
                    u64 aA = 0ull, aB = 0ull;
                    aA = ffma2(E2[ci][0], q[0], aA);
                    aB = ffma2(E2[ci][1], q[1], aB);
                    aA = ffma2(E2[ci][2], q[2], aA);
                    aB = ffma2(E2[ci][3], q[3], aB);
                    aA = ffma2(E2[ci][4], q[4], aA);
                    aB = ffma2(E2[ci][5], q[5], aB);
                    aA = ffma2(E2[ci][6], q[6], aA);
                    aB = ffma2(E2[ci][7], q[7], aB);
                    u64 a = fadd2(aA, aB);
                    float lo, hi; up2(a, lo, hi);
                    s[ci] = lo + hi;
                }
#pragma unroll
                for (int ci = 0; ci < 4; ++ci)
                    s[ci] += __shfl_xor_sync(0xffffffffu, s[ci], 8);
                Pn0 = pk2(s[0], s[1]);
                Pn1 = pk2(s[2], s[3]);
            }
            // arithmetic blend (operands share one scale; exact for m in {0,1})
            P2[0] = ffma2(mm[j], fsub2(Pn0, P2[0]), P2[0]);
            P2[1] = ffma2(mm[j], fsub2(Pn1, P2[1]), P2[1]);
            // uniform po2 rescale of the blended state
            if (j == 0){
                u64 rr = pk2(r, r);
                P2[0] = fmul2(P2[0], rr);
                P2[1] = fmul2(P2[1], rr);
            }
            // prefetch step done+4+j (clamped to last valid step)
            {
                int sn = done + 4 + j;
                int tc = (sn < n) ? (tbeg + dt * sn) : tlast;
                float4 f4 = *reinterpret_cast<const float4*>(fbase + (size_t)((unsigned)tc * fstep));
                fe[j][0] = pk2(ex2f(f4.x*LOG2E), ex2f(f4.y*LOG2E));
                fe[j][1] = pk2(ex2f(f4.z*LOG2E), ex2f(f4.w*LOG2E));
                float m = mbase[(unsigned)tc * mstep];
                mm[j] = pk2(m, m);
            }
        }
        done += 4;
    }
    // tail (n % 4 != 0; not hit for seq=512/mid=256)
    for (; done < n; ++done){
        int t = tbeg + dt * done;
        float4 f4 = *reinterpret_cast<const float4*>(fbase + (size_t)((unsigned)t * fstep));
        u64 fe0 = pk2(ex2f(f4.x*LOG2E), ex2f(f4.y*LOG2E));
        u64 fe1 = pk2(ex2f(f4.z*LOG2E), ex2f(f4.w*LOG2E));
        float m = mbase[(unsigned)t * mstep];
        u64 mv = pk2(m, m);
        u64 src0 = P2[0], src1 = P2[1];
        if (dirb != 0){ src0 = fmul2(P2[0], fe0); src1 = fmul2(P2[1], fe1); }
        u64 q[8];
#pragma unroll
        for (int qi = 0; qi < 4; ++qi){
            q[2*qi]   = shfl64(src0, xbase + qi);
            q[2*qi+1] = shfl64(src1, xbase + qi);
        }
        float s[4];
#pragma unroll
        for (int ci = 0; ci < 4; ++ci){
            u64 aA = 0ull, aB = 0ull;
#pragma unroll
            for (int kp = 0; kp < 8; kp += 2){
                aA = ffma2(E2[ci][kp],   q[kp],   aA);
                aB = ffma2(E2[ci][kp+1], q[kp+1], aB);
            }
            u64 a = fadd2(aA, aB);
            float lo, hi; up2(a, lo, hi);
            s[ci] = lo + hi;
        }
#pragma unroll
        for (int ci = 0; ci < 4; ++ci)
            s[ci] += __shfl_xor_sync(0xffffffffu, s[ci], 8);
        u64 Pn0, Pn1;
        if (dirb == 0){ Pn0 = fmul2(pk2(s[0], s[1]), fe0); Pn1 = fmul2(pk2(s[2], s[3]), fe1); }
        else          { Pn0 = pk2(s[0], s[1]);             Pn1 = pk2(s[2], s[3]); }
        P2[0] = ffma2(mv, fsub2(Pn0, P2[0]), P2[0]);
        P2[1] = ffma2(mv, fsub2(Pn1, P2[1]), P2[1]);
        {   // rescale every tail step
            float plo, phi; up2(P2[0], plo, phi);
            float piv = __shfl_sync(0xffffffffu, plo, lane & 16);
            float r = po2_rescale(piv, eC);
            u64 rr = pk2(r, r);
            P2[0] = fmul2(P2[0], rr);
            P2[1] = fmul2(P2[1], rr);
        }
    }

    // Publish half-scan result (k-partner copies identical; kh==0 writes).
    if (kh == 0 && real){
        float a0, a1, a2, a3;
        up2(P2[0], a0, a1); up2(P2[1], a2, a3);
        float4 w; w.x = a0; w.y = a1; w.z = a2; w.w = a3;
        *reinterpret_cast<float4*>(&g_vec[dirb][bb][c0]) = w;
    }
    if (g == 0 && real) g_eC[dirb][bb] = eC;
}

// out[b] = ln2 * (eC_f + eC_b + log2( sum_c P_mid[c] * u_mid[c] ))
__global__ void crf_combine(float* __restrict__ out, int batch)
{
    const int w = threadIdx.x >> 5;
    const int lane = threadIdx.x & 31;
    const int bb = blockIdx.x * 8 + w;
    if (bb >= batch) return;
    float v = g_vec[0][bb][lane] * g_vec[1][bb][lane];
#pragma unroll
    for (int off = 16; off > 0; off >>= 1)
        v += __shfl_xor_sync(0xffffffffu, v, off);
    if (lane == 0)
        out[bb] = ((float)(g_eC[0][bb] + g_eC[1][bb]) + lg2f_(v)) * LN2F;
}

extern "C" void kernel_launch(void* const* d_in, const int* in_sizes, int n_in,
                              void* d_out, int out_size)
{
    const float* feats = (const float*)d_in[0];
    const float* mask  = (const float*)d_in[1];
    const float* trans = (const float*)d_in[2];
    float* out = (float*)d_out;

    const int batch = out_size;                 // out is (batch,)
    const int seq   = in_sizes[1] / batch;      // mask is (seq, batch)
    const int mid   = seq / 2;

    const int npairs = (batch + 1) / 2;         // 2 batches per warp
    crf_scan<<<npairs * 2, 32>>>(feats, mask, trans, seq, batch, mid);
    crf_combine<<<(batch + 7) / 8, 256>>>(out, batch);
}

// round 14
// speedup vs baseline: 1.4481x; 1.4481x over previous
#include <cuda_runtime.h>

#define NCLS 32
#define SOSC 30
#define EOSC 31
#define LOG2E 1.4426950408889634f
#define LN2F  0.6931471805599453f
#define MAXB  8192

typedef unsigned long long u64;

__device__ float g_vec[2][MAXB][NCLS];   // [dir][batch][class] scan results
__device__ int   g_eC[2][MAXB];          // [dir][batch] exact log2 offsets

__device__ __forceinline__ float ex2f(float x){ float r; asm("ex2.approx.f32 %0, %1;" : "=f"(r) : "f"(x)); return r; }
__device__ __forceinline__ float lg2f_(float x){ float r; asm("lg2.approx.f32 %0, %1;" : "=f"(r) : "f"(x)); return r; }
__device__ __forceinline__ u64 pk2(float lo, float hi){ u64 r; asm("mov.b64 %0, {%1,%2};" : "=l"(r) : "f"(lo), "f"(hi)); return r; }
__device__ __forceinline__ void up2(u64 v, float& lo, float& hi){ asm("mov.b64 {%0,%1}, %2;" : "=f"(lo), "=f"(hi) : "l"(v)); }
__device__ __forceinline__ u64 ffma2(u64 a, u64 b, u64 c){ u64 d; asm("fma.rn.f32x2 %0, %1, %2, %3;" : "=l"(d) : "l"(a), "l"(b), "l"(c)); return d; }
__device__ __forceinline__ u64 fadd2(u64 a, u64 b){ u64 d; asm("add.rn.f32x2 %0, %1, %2;" : "=l"(d) : "l"(a), "l"(b)); return d; }
__device__ __forceinline__ u64 fmul2(u64 a, u64 b){ u64 d; asm("mul.rn.f32x2 %0, %1, %2;" : "=l"(d) : "l"(a), "l"(b)); return d; }
__device__ __forceinline__ u64 fsub2(u64 a, u64 b){ u64 d; asm("sub.rn.f32x2 %0, %1, %2;" : "=l"(d) : "l"(a), "l"(b)); return d; }

__device__ __forceinline__ u64 shfl64(u64 v, int src){
    float lo, hi; up2(v, lo, hi);
    lo = __shfl_sync(0xffffffffu, lo, src);
    hi = __shfl_sync(0xffffffffu, hi, src);
    return pk2(lo, hi);
}

// Exact power-of-2 rescale factor from a stale probe value d (pure ALU).
__device__ __forceinline__ float po2_rescale(float d, int& eacc){
    unsigned u = __float_as_uint(d);
    int e = (int)(u >> 23) & 0xff;
    if (e == 0 || e >= 254) return 1.0f;
    eacc += (e - 127);
    return __uint_as_float((unsigned)(254 - e) << 23);
}

// One half-scan, direction fixed at compile time (no per-step branch).
// DIRB=0: P' = m * fe o (E q) + (1-m) P     (q = exchange(P))
// DIRB=1: u' = m * E^T (exchange(u o fe)) + (1-m) u   (E2 holds E^T rows)
// Warp layout / exchange / blend / po2-rescale = the proven round-9 pattern.
template<int DIRB>
__device__ __forceinline__ void scan_body(
    const u64 E2[4][8], u64 P2[2], int& eC,
    const float* fbase, const float* mbase,
    unsigned fstep, unsigned mstep,
    int n, int tbeg, int dt, int lane, int xbase)
{
    const int tlast = tbeg + dt * (n - 1);

    // 8-deep prefetch of exp(feat) (4 classes/lane) and packed mask.
    u64 fe[8][2], mm[8];
#pragma unroll
    for (int j = 0; j < 8; ++j){
        int tc = (j < n) ? (tbeg + dt * j) : tlast;
        float4 f4 = *reinterpret_cast<const float4*>(fbase + (size_t)((unsigned)tc * fstep));
        fe[j][0] = pk2(ex2f(f4.x*LOG2E), ex2f(f4.y*LOG2E));
        fe[j][1] = pk2(ex2f(f4.z*LOG2E), ex2f(f4.w*LOG2E));
        float m = mbase[(unsigned)tc * mstep];
        mm[j] = pk2(m, m);
    }

    int done = 0;
    for (; done + 8 <= n; done += 8){
#pragma unroll
        for (int j = 0; j < 8; ++j){
            // stale rescale pivot from pre-step state (ALU+shfl, overlaps body)
            float r = 1.0f;
            if ((j & 3) == 0){
                float plo, phi; up2(P2[0], plo, phi);
                float piv = __shfl_sync(0xffffffffu, plo, lane & 16);
                r = po2_rescale(piv, eC);
            }
            u64 src0 = P2[0], src1 = P2[1];
            if (DIRB != 0){ src0 = fmul2(src0, fe[j][0]); src1 = fmul2(src1, fe[j][1]); }
            u64 q[8];
#pragma unroll
            for (int qi = 0; qi < 4; ++qi){
                q[2*qi]   = shfl64(src0, xbase + qi);
                q[2*qi+1] = shfl64(src1, xbase + qi);
            }
            float s[4];
#pragma unroll
            for (int ci = 0; ci < 4; ++ci){
                u64 aA = 0ull, aB = 0ull;
                aA = ffma2(E2[ci][0], q[0], aA);
                aB = ffma2(E2[ci][1], q[1], aB);
                aA = ffma2(E2[ci][2], q[2], aA);
                aB = ffma2(E2[ci][3], q[3], aB);
                aA = ffma2(E2[ci][4], q[4], aA);
                aB = ffma2(E2[ci][5], q[5], aB);
                aA = ffma2(E2[ci][6], q[6], aA);
                aB = ffma2(E2[ci][7], q[7], aB);
                u64 a = fadd2(aA, aB);
                float lo, hi; up2(a, lo, hi);
                s[ci] = lo + hi;
            }
#pragma unroll
            for (int ci = 0; ci < 4; ++ci)
                s[ci] += __shfl_xor_sync(0xffffffffu, s[ci], 8);
            u64 Pn0, Pn1;
            if (DIRB == 0){
                Pn0 = fmul2(pk2(s[0], s[1]), fe[j][0]);
                Pn1 = fmul2(pk2(s[2], s[3]), fe[j][1]);
            } else {
                Pn0 = pk2(s[0], s[1]);
                Pn1 = pk2(s[2], s[3]);
            }
            // arithmetic blend (operands share one scale; exact for m in {0,1})
            P2[0] = ffma2(mm[j], fsub2(Pn0, P2[0]), P2[0]);
            P2[1] = ffma2(mm[j], fsub2(Pn1, P2[1]), P2[1]);
            // uniform po2 rescale of the blended state
            if ((j & 3) == 0){
                u64 rr = pk2(r, r);
                P2[0] = fmul2(P2[0], rr);
                P2[1] = fmul2(P2[1], rr);
            }
            // prefetch step done+8+j (clamped to last valid step)
            {
                int sn = done + 8 + j;
                int tc = (sn < n) ? (tbeg + dt * sn) : tlast;
                float4 f4 = *reinterpret_cast<const float4*>(fbase + (size_t)((unsigned)tc * fstep));
                fe[j][0] = pk2(ex2f(f4.x*LOG2E), ex2f(f4.y*LOG2E));
                fe[j][1] = pk2(ex2f(f4.z*LOG2E), ex2f(f4.w*LOG2E));
                float m = mbase[(unsigned)tc * mstep];
                mm[j] = pk2(m, m);
            }
        }
    }
    // tail (n % 8 != 0; not hit for seq=512/mid=256)
    for (; done < n; ++done){
        int t = tbeg + dt * done;
        float4 f4 = *reinterpret_cast<const float4*>(fbase + (size_t)((unsigned)t * fstep));
        u64 fe0 = pk2(ex2f(f4.x*LOG2E), ex2f(f4.y*LOG2E));
        u64 fe1 = pk2(ex2f(f4.z*LOG2E), ex2f(f4.w*LOG2E));
        float m = mbase[(unsigned)t * mstep];
        u64 mv = pk2(m, m);
        u64 src0 = P2[0], src1 = P2[1];
        if (DIRB != 0){ src0 = fmul2(src0, fe0); src1 = fmul2(src1, fe1); }
        u64 q[8];
#pragma unroll
        for (int qi = 0; qi < 4; ++qi){
            q[2*qi]   = shfl64(src0, xbase + qi);
            q[2*qi+1] = shfl64(src1, xbase + qi);
        }
        float s[4];
#pragma unroll
        for (int ci = 0; ci < 4; ++ci){
            u64 aA = 0ull, aB = 0ull;
#pragma unroll
            for (int kp = 0; kp < 8; kp += 2){
                aA = ffma2(E2[ci][kp],   q[kp],   aA);
                aB = ffma2(E2[ci][kp+1], q[kp+1], aB);
            }
            u64 a = fadd2(aA, aB);
            float lo, hi; up2(a, lo, hi);
            s[ci] = lo + hi;
        }
#pragma unroll
        for (int ci = 0; ci < 4; ++ci)
            s[ci] += __shfl_xor_sync(0xffffffffu, s[ci], 8);
        u64 Pn0, Pn1;
        if (DIRB == 0){ Pn0 = fmul2(pk2(s[0], s[1]), fe0); Pn1 = fmul2(pk2(s[2], s[3]), fe1); }
        else          { Pn0 = pk2(s[0], s[1]);             Pn1 = pk2(s[2], s[3]); }
        P2[0] = ffma2(mv, fsub2(Pn0, P2[0]), P2[0]);
        P2[1] = ffma2(mv, fsub2(Pn1, P2[1]), P2[1]);
        {
            float plo, phi; up2(P2[0], plo, phi);
            float piv = __shfl_sync(0xffffffffu, plo, lane & 16);
            float r = po2_rescale(piv, eC);
            u64 rr = pk2(r, r);
            P2[0] = fmul2(P2[0], rr);
            P2[1] = fmul2(P2[1], rr);
        }
    }
}

// Bidirectional exp-domain CRF scan (linear-map splitting):
//   answer = log(u^T M_{seq-1}...M_0 P_0), split at mid into two half-scans.
// Even blocks: forward P_mid; odd blocks: backward u_mid. 2 batches per warp.
__global__ __launch_bounds__(32, 8)
void crf_scan(const float* __restrict__ feats,
              const float* __restrict__ mask,
              const float* __restrict__ trans,
              int seq, int batch, int mid)
{
    const int lane = threadIdx.x & 31;
    const int b    = lane >> 4;
    const int g    = lane & 15;
    const int gc   = g & 7;
    const int kh   = g >> 3;
    const int c0   = gc * 4;
    const int k0   = kh * 16;
    const int dirb = blockIdx.x & 1;  // 0 = forward, 1 = backward
    const int pair = blockIdx.x >> 1;
    int bb = pair * 2 + b;
    const bool real = (bb < batch);
    if (!real) bb = batch - 1;
    const int xbase = (lane & 16) | (kh << 2);

    // E2: forward = rows of exp(T); backward = rows of exp(T)^T.
    u64 E2[4][8];
    if (dirb == 0){
#pragma unroll
        for (int ci = 0; ci < 4; ++ci){
            const float* tr = trans + (c0 + ci) * NCLS + k0;
#pragma unroll
            for (int kp = 0; kp < 8; ++kp)
                E2[ci][kp] = pk2(ex2f(tr[2*kp] * LOG2E), ex2f(tr[2*kp+1] * LOG2E));
        }
    } else {
#pragma unroll
        for (int ci = 0; ci < 4; ++ci){
#pragma unroll
            for (int kp = 0; kp < 8; ++kp)
                E2[ci][kp] = pk2(ex2f(trans[(k0 + 2*kp    ) * NCLS + c0 + ci] * LOG2E),
                                 ex2f(trans[(k0 + 2*kp + 1) * NCLS + c0 + ci] * LOG2E));
        }
    }

    u64 P2[2];
    if (dirb == 0){
        P2[0] = pk2((c0+0==SOSC)?1.f:0.f, (c0+1==SOSC)?1.f:0.f);
        P2[1] = pk2((c0+2==SOSC)?1.f:0.f, (c0+3==SOSC)?1.f:0.f);
    } else {
        const float* te = trans + EOSC * NCLS + c0;
        P2[0] = pk2(ex2f(te[0]*LOG2E), ex2f(te[1]*LOG2E));
        P2[1] = pk2(ex2f(te[2]*LOG2E), ex2f(te[3]*LOG2E));
    }
    int eC = 0;

    const float* fbase = feats + (size_t)bb * NCLS + c0;
    const float* mbase = mask + bb;
    const unsigned fstep = (unsigned)batch * NCLS;
    const unsigned mstep = (unsigned)batch;

    if (dirb == 0)
        scan_body<0>(E2, P2, eC, fbase, mbase, fstep, mstep,
                     mid, 0, 1, lane, xbase);
    else
        scan_body<1>(E2, P2, eC, fbase, mbase, fstep, mstep,
                     seq - mid, seq - 1, -1, lane, xbase);

    // Publish half-scan result (k-partner copies identical; kh==0 writes).
    if (kh == 0 && real){
        float a0, a1, a2, a3;
        up2(P2[0], a0, a1); up2(P2[1], a2, a3);
        float4 w; w.x = a0; w.y = a1; w.z = a2; w.w = a3;
        *reinterpret_cast<float4*>(&g_vec[dirb][bb][c0]) = w;
    }
    if (g == 0 && real) g_eC[dirb][bb] = eC;
}

// out[b] = ln2 * (eC_f + eC_b + log2( sum_c P_mid[c] * u_mid[c] ))
__global__ void crf_combine(float* __restrict__ out, int batch)
{
    const int w = threadIdx.x >> 5;
    const int lane = threadIdx.x & 31;
    const int bb = blockIdx.x * 8 + w;
    if (bb >= batch) return;
    float v = g_vec[0][bb][lane] * g_vec[1][bb][lane];
#pragma unroll
    for (int off = 16; off > 0; off >>= 1)
        v += __shfl_xor_sync(0xffffffffu, v, off);
    if (lane == 0)
        out[bb] = ((float)(g_eC[0][bb] + g_eC[1][bb]) + lg2f_(v)) * LN2F;
}

extern "C" void kernel_launch(void* const* d_in, const int* in_sizes, int n_in,
                              void* d_out, int out_size)
{
    const float* feats = (const float*)d_in[0];
    const float* mask  = (const float*)d_in[1];
    const float* trans = (const float*)d_in[2];
    float* out = (float*)d_out;

    const int batch = out_size;                 // out is (batch,)
    const int seq   = in_sizes[1] / batch;      // mask is (seq, batch)
    const int mid   = seq / 2;

    const int npairs = (batch + 1) / 2;         // 2 batches per warp
    crf_scan<<<npairs * 2, 32>>>(feats, mask, trans, seq, batch, mid);
    crf_combine<<<(batch + 7) / 8, 256>>>(out, batch);
}

// round 15
// speedup vs baseline: 1.5964x; 1.1025x over previous
#include <cuda_runtime.h>

#define NCLS 32
#define SOSC 30
#define EOSC 31
#define LOG2E 1.4426950408889634f
#define LN2F  0.6931471805599453f
#define MAXB  8192

typedef unsigned long long u64;

__device__ float g_vec[2][MAXB][NCLS];   // [dir][batch][class] scan results
__device__ int   g_eC[2][MAXB];          // [dir][batch] exact log2 offsets

__device__ __forceinline__ float ex2f(float x){ float r; asm("ex2.approx.f32 %0, %1;" : "=f"(r) : "f"(x)); return r; }
__device__ __forceinline__ float lg2f_(float x){ float r; asm("lg2.approx.f32 %0, %1;" : "=f"(r) : "f"(x)); return r; }
__device__ __forceinline__ u64 pk2(float lo, float hi){ u64 r; asm("mov.b64 %0, {%1,%2};" : "=l"(r) : "f"(lo), "f"(hi)); return r; }
__device__ __forceinline__ void up2(u64 v, float& lo, float& hi){ asm("mov.b64 {%0,%1}, %2;" : "=f"(lo), "=f"(hi) : "l"(v)); }
__device__ __forceinline__ u64 ffma2(u64 a, u64 b, u64 c){ u64 d; asm("fma.rn.f32x2 %0, %1, %2, %3;" : "=l"(d) : "l"(a), "l"(b), "l"(c)); return d; }
__device__ __forceinline__ u64 fadd2(u64 a, u64 b){ u64 d; asm("add.rn.f32x2 %0, %1, %2;" : "=l"(d) : "l"(a), "l"(b)); return d; }
__device__ __forceinline__ u64 fmul2(u64 a, u64 b){ u64 d; asm("mul.rn.f32x2 %0, %1, %2;" : "=l"(d) : "l"(a), "l"(b)); return d; }
__device__ __forceinline__ u64 fsub2(u64 a, u64 b){ u64 d; asm("sub.rn.f32x2 %0, %1, %2;" : "=l"(d) : "l"(a), "l"(b)); return d; }

__device__ __forceinline__ u64 shfl64(u64 v, int src){
    float lo, hi; up2(v, lo, hi);
    lo = __shfl_sync(0xffffffffu, lo, src);
    hi = __shfl_sync(0xffffffffu, hi, src);
    return pk2(lo, hi);
}

// Exact power-of-2 rescale factor from a stale probe value d (pure ALU).
__device__ __forceinline__ float po2_rescale(float d, int& eacc){
    unsigned u = __float_as_uint(d);
    int e = (int)(u >> 23) & 0xff;
    if (e == 0 || e >= 254) return 1.0f;
    eacc += (e - 127);
    return __uint_as_float((unsigned)(254 - e) << 23);
}

// One half-scan, direction fixed at compile time (no per-step branch).
// DIRB=0: P' = m * fe o (E q) + (1-m) P      (q = exchange(P))
// DIRB=1: u' = m * E^T (exchange(u o fe)) + (1-m) u   (E2 holds E^T rows)
// Warp layout / exchange / blend / po2-rescale = the proven round-9 pattern.
// Register budget target: <=146 (14 CTAs/SM, single wave for 2048 CTAs) —
// hence 4-deep prefetch and scalar mask storage.
template<int DIRB>
__device__ __forceinline__ void scan_body(
    const u64 E2[4][8], u64 P2[2], int& eC,
    const float* fbase, const float* mbase,
    unsigned fstep, unsigned mstep,
    int n, int tbeg, int dt, int lane, int xbase)
{
    const int tlast = tbeg + dt * (n - 1);

    // 4-deep prefetch of exp(feat) (4 classes/lane) and scalar mask.
    u64 fe[4][2]; float mk[4];
#pragma unroll
    for (int j = 0; j < 4; ++j){
        int tc = (j < n) ? (tbeg + dt * j) : tlast;
        float4 f4 = *reinterpret_cast<const float4*>(fbase + (size_t)((unsigned)tc * fstep));
        fe[j][0] = pk2(ex2f(f4.x*LOG2E), ex2f(f4.y*LOG2E));
        fe[j][1] = pk2(ex2f(f4.z*LOG2E), ex2f(f4.w*LOG2E));
        mk[j] = mbase[(unsigned)tc * mstep];
    }

    int done = 0;
    for (; done + 4 <= n; done += 4){
#pragma unroll
        for (int j = 0; j < 4; ++j){
            // stale rescale pivot from pre-step state (ALU+shfl, overlaps body)
            float r = 1.0f;
            if (j == 0){
                float plo, phi; up2(P2[0], plo, phi);
                float piv = __shfl_sync(0xffffffffu, plo, lane & 16);
                r = po2_rescale(piv, eC);
            }
            u64 src0 = P2[0], src1 = P2[1];
            if (DIRB != 0){ src0 = fmul2(src0, fe[j][0]); src1 = fmul2(src1, fe[j][1]); }
            u64 q[8];
#pragma unroll
            for (int qi = 0; qi < 4; ++qi){
                q[2*qi]   = shfl64(src0, xbase + qi);
                q[2*qi+1] = shfl64(src1, xbase + qi);
            }
            float s[4];
#pragma unroll
            for (int ci = 0; ci < 4; ++ci){
                u64 aA = 0ull, aB = 0ull;
                aA = ffma2(E2[ci][0], q[0], aA);
                aB = ffma2(E2[ci][1], q[1], aB);
                aA = ffma2(E2[ci][2], q[2], aA);
                aB = ffma2(E2[ci][3], q[3], aB);
                aA = ffma2(E2[ci][4], q[4], aA);
                aB = ffma2(E2[ci][5], q[5], aB);
                aA = ffma2(E2[ci][6], q[6], aA);
                aB = ffma2(E2[ci][7], q[7], aB);
                u64 a = fadd2(aA, aB);
                float lo, hi; up2(a, lo, hi);
                s[ci] = lo + hi;
            }
#pragma unroll
            for (int ci = 0; ci < 4; ++ci)
                s[ci] += __shfl_xor_sync(0xffffffffu, s[ci], 8);
            u64 Pn0, Pn1;
            if (DIRB == 0){
                Pn0 = fmul2(pk2(s[0], s[1]), fe[j][0]);
                Pn1 = fmul2(pk2(s[2], s[3]), fe[j][1]);
            } else {
                Pn0 = pk2(s[0], s[1]);
                Pn1 = pk2(s[2], s[3]);
            }
            // arithmetic blend (operands share one scale; exact for m in {0,1})
            u64 mm = pk2(mk[j], mk[j]);
            P2[0] = ffma2(mm, fsub2(Pn0, P2[0]), P2[0]);
            P2[1] = ffma2(mm, fsub2(Pn1, P2[1]), P2[1]);
            // uniform po2 rescale of the blended state
            if (j == 0){
                u64 rr = pk2(r, r);
                P2[0] = fmul2(P2[0], rr);
                P2[1] = fmul2(P2[1], rr);
            }
            // prefetch step done+4+j (clamped to last valid step)
            {
                int sn = done + 4 + j;
                int tc = (sn < n) ? (tbeg + dt * sn) : tlast;
                float4 f4 = *reinterpret_cast<const float4*>(fbase + (size_t)((unsigned)tc * fstep));
                fe[j][0] = pk2(ex2f(f4.x*LOG2E), ex2f(f4.y*LOG2E));
                fe[j][1] = pk2(ex2f(f4.z*LOG2E), ex2f(f4.w*LOG2E));
                mk[j] = mbase[(unsigned)tc * mstep];
            }
        }
    }
    // tail (n % 4 != 0; not hit for seq=512/mid=256)
    for (; done < n; ++done){
        int t = tbeg + dt * done;
        float4 f4 = *reinterpret_cast<const float4*>(fbase + (size_t)((unsigned)t * fstep));
        u64 fe0 = pk2(ex2f(f4.x*LOG2E), ex2f(f4.y*LOG2E));
        u64 fe1 = pk2(ex2f(f4.z*LOG2E), ex2f(f4.w*LOG2E));
        float m = mbase[(unsigned)t * mstep];
        u64 mv = pk2(m, m);
        u64 src0 = P2[0], src1 = P2[1];
        if (DIRB != 0){ src0 = fmul2(src0, fe0); src1 = fmul2(src1, fe1); }
        u64 q[8];
#pragma unroll
        for (int qi = 0; qi < 4; ++qi){
            q[2*qi]   = shfl64(src0, xbase + qi);
            q[2*qi+1] = shfl64(src1, xbase + qi);
        }
        float s[4];
#pragma unroll
        for (int ci = 0; ci < 4; ++ci){
            u64 aA = 0ull, aB = 0ull;
#pragma unroll
            for (int kp = 0; kp < 8; kp += 2){
                aA = ffma2(E2[ci][kp],   q[kp],   aA);
                aB = ffma2(E2[ci][kp+1], q[kp+1], aB);
            }
            u64 a = fadd2(aA, aB);
            float lo, hi; up2(a, lo, hi);
            s[ci] = lo + hi;
        }
#pragma unroll
        for (int ci = 0; ci < 4; ++ci)
            s[ci] += __shfl_xor_sync(0xffffffffu, s[ci], 8);
        u64 Pn0, Pn1;
        if (DIRB == 0){ Pn0 = fmul2(pk2(s[0], s[1]), fe0); Pn1 = fmul2(pk2(s[2], s[3]), fe1); }
        else          { Pn0 = pk2(s[0], s[1]);             Pn1 = pk2(s[2], s[3]); }
        P2[0] = ffma2(mv, fsub2(Pn0, P2[0]), P2[0]);
        P2[1] = ffma2(mv, fsub2(Pn1, P2[1]), P2[1]);
        {
            float plo, phi; up2(P2[0], plo, phi);
            float piv = __shfl_sync(0xffffffffu, plo, lane & 16);
            float r = po2_rescale(piv, eC);
            u64 rr = pk2(r, r);
            P2[0] = fmul2(P2[0], rr);
            P2[1] = fmul2(P2[1], rr);
        }
    }
}

// Bidirectional exp-domain CRF scan (linear-map splitting):
//   answer = log(u^T M_{seq-1}...M_0 P_0), split at mid into two half-scans.
// Even blocks: forward P_mid; odd blocks: backward u_mid. 2 batches per warp.
// 14 CTAs/SM (regs<=146) -> 2048 CTAs fit in ONE wave on 148 SMs.
__global__ __launch_bounds__(32, 14)
void crf_scan(const float* __restrict__ feats,
              const float* __restrict__ mask,
              const float* __restrict__ trans,
              int seq, int batch, int mid)
{
    const int lane = threadIdx.x & 31;
    const int b    = lane >> 4;
    const int g    = lane & 15;
    const int gc   = g & 7;
    const int kh   = g >> 3;
    const int c0   = gc * 4;
    const int k0   = kh * 16;
    const int dirb = blockIdx.x & 1;  // 0 = forward, 1 = backward
    const int pair = blockIdx.x >> 1;
    int bb = pair * 2 + b;
    const bool real = (bb < batch);
    if (!real) bb = batch - 1;
    const int xbase = (lane & 16) | (kh << 2);

    // E2: forward = rows of exp(T); backward = rows of exp(T)^T.
    u64 E2[4][8];
    if (dirb == 0){
#pragma unroll
        for (int ci = 0; ci < 4; ++ci){
            const float* tr = trans + (c0 + ci) * NCLS + k0;
#pragma unroll
            for (int kp = 0; kp < 8; ++kp)
                E2[ci][kp] = pk2(ex2f(tr[2*kp] * LOG2E), ex2f(tr[2*kp+1] * LOG2E));
        }
    } else {
#pragma unroll
        for (int ci = 0; ci < 4; ++ci){
#pragma unroll
            for (int kp = 0; kp < 8; ++kp)
                E2[ci][kp] = pk2(ex2f(trans[(k0 + 2*kp    ) * NCLS + c0 + ci] * LOG2E),
                                 ex2f(trans[(k0 + 2*kp + 1) * NCLS + c0 + ci] * LOG2E));
        }
    }

    u64 P2[2];
    if (dirb == 0){
        P2[0] = pk2((c0+0==SOSC)?1.f:0.f, (c0+1==SOSC)?1.f:0.f);
        P2[1] = pk2((c0+2==SOSC)?1.f:0.f, (c0+3==SOSC)?1.f:0.f);
    } else {
        const float* te = trans + EOSC * NCLS + c0;
        P2[0] = pk2(ex2f(te[0]*LOG2E), ex2f(te[1]*LOG2E));
        P2[1] = pk2(ex2f(te[2]*LOG2E), ex2f(te[3]*LOG2E));
    }
    int eC = 0;

    const float* fbase = feats + (size_t)bb * NCLS + c0;
    const float* mbase = mask + bb;
    const unsigned fstep = (unsigned)batch * NCLS;
    const unsigned mstep = (unsigned)batch;

    if (dirb == 0)
        scan_body<0>(E2, P2, eC, fbase, mbase, fstep, mstep,
                     mid, 0, 1, lane, xbase);
    else
        scan_body<1>(E2, P2, eC, fbase, mbase, fstep, mstep,
                     seq - mid, seq - 1, -1, lane, xbase);

    // Publish half-scan result (k-partner copies identical; kh==0 writes).
    if (kh == 0 && real){
        float a0, a1, a2, a3;
        up2(P2[0], a0, a1); up2(P2[1], a2, a3);
        float4 w; w.x = a0; w.y = a1; w.z = a2; w.w = a3;
        *reinterpret_cast<float4*>(&g_vec[dirb][bb][c0]) = w;
    }
    if (g == 0 && real) g_eC[dirb][bb] = eC;
}

// out[b] = ln2 * (eC_f + eC_b + log2( sum_c P_mid[c] * u_mid[c] ))
__global__ void crf_combine(float* __restrict__ out, int batch)
{
    const int w = threadIdx.x >> 5;
    const int lane = threadIdx.x & 31;
    const int bb = blockIdx.x * 8 + w;
    if (bb >= batch) return;
    float v = g_vec[0][bb][lane] * g_vec[1][bb][lane];
#pragma unroll
    for (int off = 16; off > 0; off >>= 1)
        v += __shfl_xor_sync(0xffffffffu, v, off);
    if (lane == 0)
        out[bb] = ((float)(g_eC[0][bb] + g_eC[1][bb]) + lg2f_(v)) * LN2F;
}

extern "C" void kernel_launch(void* const* d_in, const int* in_sizes, int n_in,
                              void* d_out, int out_size)
{
    const float* feats = (const float*)d_in[0];
    const float* mask  = (const float*)d_in[1];
    const float* trans = (const float*)d_in[2];
    float* out = (float*)d_out;

    const int batch = out_size;                 // out is (batch,)
    const int seq   = in_sizes[1] / batch;      // mask is (seq, batch)
    const int mid   = seq / 2;

    const int npairs = (batch + 1) / 2;         // 2 batches per warp
    crf_scan<<<npairs * 2, 32>>>(feats, mask, trans, seq, batch, mid);
    crf_combine<<<(batch + 7) / 8, 256>>>(out, batch);
}

// round 16
// speedup vs baseline: 1.6245x; 1.0176x over previous
#include <cuda_runtime.h>

#define NCLS 32
#define SOSC 30
#define EOSC 31
#define LOG2E 1.4426950408889634f
#define LN2F  0.6931471805599453f
#define MAXB  8192

typedef unsigned long long u64;

__device__ float g_vec[2][MAXB][NCLS];   // [dir][batch][class] scan results
__device__ int   g_eC[2][MAXB];          // [dir][batch] exact log2 offsets

__device__ __forceinline__ float ex2f(float x){ float r; asm("ex2.approx.f32 %0, %1;" : "=f"(r) : "f"(x)); return r; }
__device__ __forceinline__ float lg2f_(float x){ float r; asm("lg2.approx.f32 %0, %1;" : "=f"(r) : "f"(x)); return r; }
__device__ __forceinline__ u64 pk2(float lo, float hi){ u64 r; asm("mov.b64 %0, {%1,%2};" : "=l"(r) : "f"(lo), "f"(hi)); return r; }
__device__ __forceinline__ void up2(u64 v, float& lo, float& hi){ asm("mov.b64 {%0,%1}, %2;" : "=f"(lo), "=f"(hi) : "l"(v)); }
__device__ __forceinline__ u64 ffma2(u64 a, u64 b, u64 c){ u64 d; asm("fma.rn.f32x2 %0, %1, %2, %3;" : "=l"(d) : "l"(a), "l"(b), "l"(c)); return d; }
__device__ __forceinline__ u64 fadd2(u64 a, u64 b){ u64 d; asm("add.rn.f32x2 %0, %1, %2;" : "=l"(d) : "l"(a), "l"(b)); return d; }
__device__ __forceinline__ u64 fmul2(u64 a, u64 b){ u64 d; asm("mul.rn.f32x2 %0, %1, %2;" : "=l"(d) : "l"(a), "l"(b)); return d; }
__device__ __forceinline__ u64 fsub2(u64 a, u64 b){ u64 d; asm("sub.rn.f32x2 %0, %1, %2;" : "=l"(d) : "l"(a), "l"(b)); return d; }

// Exact power-of-2 rescale factor from a stale probe value d (pure ALU).
__device__ __forceinline__ float po2_rescale(float d, int& eacc){
    unsigned u = __float_as_uint(d);
    int e = (int)(u >> 23) & 0xff;
    if (e == 0 || e >= 254) return 1.0f;
    eacc += (e - 127);
    return __uint_as_float((unsigned)(254 - e) << 23);
}

// One half-scan over n steps, direction fixed at compile time.
// Layout (R7, MIO-minimal): warp = 4 batches; 8 lanes/batch; lane owns 4
// classes (c0..c0+3) with FULL k=32 dots (no partner reduce). Exchange via
// smem: 1 STS.128 + 8 LDS.128 per lane per step (2.75 MIO/batch-step).
// DIRB=0: P' = m * fe o (E q) + (1-m) P        (store P, q = batch's 32 P)
// DIRB=1: u' = m * E^T(exchange(u o fe)) + (1-m) u  (E2 holds E^T rows)
// Numerics: exp-domain, blend-then-po2-rescale every 4 steps, stale pivot.
template<int DIRB>
__device__ __forceinline__ void scan_body(
    const u64 E2[4][16], u64 P2[2], int& eC,
    const float* fbase, const float* mbase,
    unsigned fstep, unsigned mstep,
    int n, int tbeg, int dt, int lane,
    float* stbase, const float* ldbase, int dstride)
{
    const int tlast = tbeg + dt * (n - 1);

    // 4-deep prefetch of exp(feat) (4 classes/lane) and scalar mask.
    u64 fe[4][2]; float mk[4];
#pragma unroll
    for (int j = 0; j < 4; ++j){
        int tc = (j < n) ? (tbeg + dt * j) : tlast;
        float4 f4 = *reinterpret_cast<const float4*>(fbase + (size_t)((unsigned)tc * fstep));
        fe[j][0] = pk2(ex2f(f4.x*LOG2E), ex2f(f4.y*LOG2E));
        fe[j][1] = pk2(ex2f(f4.z*LOG2E), ex2f(f4.w*LOG2E));
        mk[j] = mbase[(unsigned)tc * mstep];
    }

    int done = 0;
    for (; done + 4 <= n; done += 4){
#pragma unroll
        for (int j = 0; j < 4; ++j){
            // stale rescale pivot (pre-step P[class 0] of this batch)
            float r = 1.0f;
            if (j == 0){
                float plo, phi; up2(P2[0], plo, phi);
                float piv = __shfl_sync(0xffffffffu, plo, lane & 24);
                r = po2_rescale(piv, eC);
            }
            u64 s0 = P2[0], s1 = P2[1];
            if (DIRB != 0){ s0 = fmul2(s0, fe[j][0]); s1 = fmul2(s1, fe[j][1]); }
            // publish this lane's 4 values (one STS.128)
            {
                ulonglong2 v; v.x = s0; v.y = s1;
                *reinterpret_cast<ulonglong2*>(stbase + (j & 1) * dstride) = v;
            }
            __syncwarp();
            const float* ld = ldbase + (j & 1) * dstride;
            u64 q[16];
#pragma unroll
            for (int si = 0; si < 8; ++si){
                ulonglong2 v = *reinterpret_cast<const ulonglong2*>(ld + si * 4);
                q[2*si]   = v.x;
                q[2*si+1] = v.y;
            }
            float s[4];
#pragma unroll
            for (int ci = 0; ci < 4; ++ci){
                u64 aA = 0ull, aB = 0ull;
#pragma unroll
                for (int kp = 0; kp < 16; kp += 2){
                    aA = ffma2(E2[ci][kp],   q[kp],   aA);
                    aB = ffma2(E2[ci][kp+1], q[kp+1], aB);
                }
                u64 a = fadd2(aA, aB);
                float lo, hi; up2(a, lo, hi);
                s[ci] = lo + hi;                 // full 32-k dot, no reduce
            }
            u64 Pn0, Pn1;
            if (DIRB == 0){
                Pn0 = fmul2(pk2(s[0], s[1]), fe[j][0]);
                Pn1 = fmul2(pk2(s[2], s[3]), fe[j][1]);
            } else {
                Pn0 = pk2(s[0], s[1]);
                Pn1 = pk2(s[2], s[3]);
            }
            // arithmetic blend (operands share one scale; exact for m in {0,1})
            u64 mm = pk2(mk[j], mk[j]);
            P2[0] = ffma2(mm, fsub2(Pn0, P2[0]), P2[0]);
            P2[1] = ffma2(mm, fsub2(Pn1, P2[1]), P2[1]);
            // uniform po2 rescale of the blended state
            if (j == 0){
                u64 rr = pk2(r, r);
                P2[0] = fmul2(P2[0], rr);
                P2[1] = fmul2(P2[1], rr);
            }
            // prefetch step done+4+j (clamped to last valid step)
            {
                int sn = done + 4 + j;
                int tc = (sn < n) ? (tbeg + dt * sn) : tlast;
                float4 f4 = *reinterpret_cast<const float4*>(fbase + (size_t)((unsigned)tc * fstep));
                fe[j][0] = pk2(ex2f(f4.x*LOG2E), ex2f(f4.y*LOG2E));
                fe[j][1] = pk2(ex2f(f4.z*LOG2E), ex2f(f4.w*LOG2E));
                mk[j] = mbase[(unsigned)tc * mstep];
            }
        }
    }
    // tail (n % 4 != 0; not hit for seq=512/mid=256)
    for (; done < n; ++done){
        int t = tbeg + dt * done;
        float4 f4 = *reinterpret_cast<const float4*>(fbase + (size_t)((unsigned)t * fstep));
        u64 fe0 = pk2(ex2f(f4.x*LOG2E), ex2f(f4.y*LOG2E));
        u64 fe1 = pk2(ex2f(f4.z*LOG2E), ex2f(f4.w*LOG2E));
        float m = mbase[(unsigned)t * mstep];
        u64 mv = pk2(m, m);
        u64 s0 = P2[0], s1 = P2[1];
        if (DIRB != 0){ s0 = fmul2(s0, fe0); s1 = fmul2(s1, fe1); }
        {
            ulonglong2 v; v.x = s0; v.y = s1;
            *reinterpret_cast<ulonglong2*>(stbase + (done & 1) * dstride) = v;
        }
        __syncwarp();
        const float* ld = ldbase + (done & 1) * dstride;
        u64 q[16];
#pragma unroll
        for (int si = 0; si < 8; ++si){
            ulonglong2 v = *reinterpret_cast<const ulonglong2*>(ld + si * 4);
            q[2*si]   = v.x;
            q[2*si+1] = v.y;
        }
        float s[4];
#pragma unroll
        for (int ci = 0; ci < 4; ++ci){
            u64 aA = 0ull, aB = 0ull;
#pragma unroll
            for (int kp = 0; kp < 16; kp += 2){
                aA = ffma2(E2[ci][kp],   q[kp],   aA);
                aB = ffma2(E2[ci][kp+1], q[kp+1], aB);
            }
            u64 a = fadd2(aA, aB);
            float lo, hi; up2(a, lo, hi);
            s[ci] = lo + hi;
        }
        u64 Pn0, Pn1;
        if (DIRB == 0){ Pn0 = fmul2(pk2(s[0], s[1]), fe0); Pn1 = fmul2(pk2(s[2], s[3]), fe1); }
        else          { Pn0 = pk2(s[0], s[1]);             Pn1 = pk2(s[2], s[3]); }
        P2[0] = ffma2(mv, fsub2(Pn0, P2[0]), P2[0]);
        P2[1] = ffma2(mv, fsub2(Pn1, P2[1]), P2[1]);
        {
            float plo, phi; up2(P2[0], plo, phi);
            float piv = __shfl_sync(0xffffffffu, plo, lane & 24);
            float r = po2_rescale(piv, eC);
            u64 rr = pk2(r, r);
            P2[0] = fmul2(P2[0], rr);
            P2[1] = fmul2(P2[1], rr);
        }
    }
}

// Bidirectional exp-domain CRF scan. CTA = one batch-quad, 2 warps:
// warp 0 = forward half-scan (P_mid), warp 1 = backward half-scan (u_mid).
__global__ __launch_bounds__(64, 4)
void crf_scan(const float* __restrict__ feats,
              const float* __restrict__ mask,
              const float* __restrict__ trans,
              int seq, int batch, int mid)
{
    __shared__ __align__(16) float pbuf[2][2][4][36];  // [warp][dbl][batch][36]
    const int tid  = threadIdx.x;
    const int wid  = tid >> 5;        // 0 = forward, 1 = backward
    const int lane = tid & 31;
    const int b    = lane >> 3;       // batch slot in warp (0..3)
    const int g    = lane & 7;        // class group -> classes 4g..4g+3
    const int c0   = g * 4;
    int bb = blockIdx.x * 4 + b;
    const bool real = (bb < batch);
    if (!real) bb = batch - 1;

    // E2: fwd = rows of exp(T); bwd = rows of exp(T)^T. 4 classes x 16 kp.
    u64 E2[4][16];
    if (wid == 0){
#pragma unroll
        for (int ci = 0; ci < 4; ++ci){
            const float* tr = trans + (c0 + ci) * NCLS;
#pragma unroll
            for (int kp = 0; kp < 16; ++kp)
                E2[ci][kp] = pk2(ex2f(tr[2*kp] * LOG2E), ex2f(tr[2*kp+1] * LOG2E));
        }
    } else {
#pragma unroll
        for (int ci = 0; ci < 4; ++ci){
#pragma unroll
            for (int kp = 0; kp < 16; ++kp)
                E2[ci][kp] = pk2(ex2f(trans[(2*kp    ) * NCLS + c0 + ci] * LOG2E),
                                 ex2f(trans[(2*kp + 1) * NCLS + c0 + ci] * LOG2E));
        }
    }

    u64 P2[2];
    if (wid == 0){
        P2[0] = pk2((c0+0==SOSC)?1.f:0.f, (c0+1==SOSC)?1.f:0.f);
        P2[1] = pk2((c0+2==SOSC)?1.f:0.f, (c0+3==SOSC)?1.f:0.f);
    } else {
        const float* te = trans + EOSC * NCLS + c0;
        P2[0] = pk2(ex2f(te[0]*LOG2E), ex2f(te[1]*LOG2E));
        P2[1] = pk2(ex2f(te[2]*LOG2E), ex2f(te[3]*LOG2E));
    }
    int eC = 0;

    const float* fbase = feats + (size_t)bb * NCLS + c0;
    const float* mbase = mask + bb;
    const unsigned fstep = (unsigned)batch * NCLS;
    const unsigned mstep = (unsigned)batch;

    float* const stbase = &pbuf[wid][0][b][c0];
    const float* const ldbase = &pbuf[wid][0][b][0];
    const int dstride = 4 * 36;

    if (wid == 0)
        scan_body<0>(E2, P2, eC, fbase, mbase, fstep, mstep,
                     mid, 0, 1, lane, stbase, ldbase, dstride);
    else
        scan_body<1>(E2, P2, eC, fbase, mbase, fstep, mstep,
                     seq - mid, seq - 1, -1, lane, stbase, ldbase, dstride);

    // Publish half-scan result: each lane stores its 4 classes.
    if (real){
        float a0, a1, a2, a3;
        up2(P2[0], a0, a1); up2(P2[1], a2, a3);
        float4 w; w.x = a0; w.y = a1; w.z = a2; w.w = a3;
        *reinterpret_cast<float4*>(&g_vec[wid][bb][c0]) = w;
        if (g == 0) g_eC[wid][bb] = eC;
    }
}

// out[b] = ln2 * (eC_f + eC_b + log2( sum_c P_mid[c] * u_mid[c] ))
__global__ void crf_combine(float* __restrict__ out, int batch)
{
    const int w = threadIdx.x >> 5;
    const int lane = threadIdx.x & 31;
    const int bb = blockIdx.x * 8 + w;
    if (bb >= batch) return;
    float v = g_vec[0][bb][lane] * g_vec[1][bb][lane];
#pragma unroll
    for (int off = 16; off > 0; off >>= 1)
        v += __shfl_xor_sync(0xffffffffu, v, off);
    if (lane == 0)
        out[bb] = ((float)(g_eC[0][bb] + g_eC[1][bb]) + lg2f_(v)) * LN2F;
}

extern "C" void kernel_launch(void* const* d_in, const int* in_sizes, int n_in,
                              void* d_out, int out_size)
{
    const float* feats = (const float*)d_in[0];
    const float* mask  = (const float*)d_in[1];
    const float* trans = (const float*)d_in[2];
    float* out = (float*)d_out;

    const int batch = out_size;                 // out is (batch,)
    const int seq   = in_sizes[1] / batch;      // mask is (seq, batch)
    const int mid   = seq / 2;

    const int nquads = (batch + 3) / 4;         // CTA = batch-quad, 2 warps
    crf_scan<<<nquads, 64>>>(feats, mask, trans, seq, batch, mid);
    crf_combine<<<(batch + 7) / 8, 256>>>(out, batch);
}